// round 1
// baseline (speedup 1.0000x reference)
#include <cuda_runtime.h>
#include <math.h>

#define BATCH 768
#define NS 32
#define NP 24
#define EDIM 64
#define HDIM 128
#define G4 512      // 4*HDIM
#define P1D 512     // pool hidden
#define BNK 1024
#define MLPD 1024
#define TSTEPS 12
#define KC 16

// ---------------- scratch (static device memory; no allocations) ----------------
__device__ float g_pos[BATCH * 2];
__device__ float g_decin[BATCH * EDIM];
__device__ float g_h[BATCH * HDIM];
__device__ float g_c[BATCH * HDIM];
__device__ float g_hmid[BATCH * HDIM];
__device__ float g_hterm[BATCH * P1D];
__device__ float g_y[(size_t)BATCH * NP * P1D];   // 18432 x 512 = 37.75 MB
__device__ float g_pool[(size_t)BATCH * BNK];
__device__ float g_dh[(size_t)BATCH * MLPD];
__device__ float g_M2[2 * P1D];
__device__ float g_cb[P1D];

__device__ __forceinline__ float sigf(float x) { return 1.f / (1.f + expf(-x)); }

typedef unsigned long long u64;
__device__ __forceinline__ u64 ffma2(u64 a, u64 b, u64 c) {
    u64 d;
    asm("fma.rn.f32x2 %0, %1, %2, %3;" : "=l"(d) : "l"(a), "l"(b), "l"(c));
    return d;
}
__device__ __forceinline__ u64 pack2(float x) {
    u64 d;
    asm("mov.b64 %0, {%1, %1};" : "=l"(d) : "f"(x));
    return d;
}
__device__ __forceinline__ void unpack2(u64 v, float& lo, float& hi) {
    asm("mov.b64 {%0, %1}, %2;" : "=f"(lo), "=f"(hi) : "l"(v));
}

// ---------------- setup: init state, fold W_pse@W_p1a, initial dec_in ----------------
__global__ void setup_kernel(const float* __restrict__ last_pos,
                             const float* __restrict__ last_pos_rel,
                             const float* __restrict__ h0, const float* __restrict__ c0,
                             const float* __restrict__ W_se, const float* __restrict__ b_se,
                             const float* __restrict__ W_pse, const float* __restrict__ b_pse,
                             const float* __restrict__ W_p1, const float* __restrict__ b_p1) {
    int tid = blockIdx.x * blockDim.x + threadIdx.x;
    int nt = gridDim.x * blockDim.x;
    for (int i = tid; i < BATCH * 2; i += nt) g_pos[i] = last_pos[i];
    for (int i = tid; i < BATCH * HDIM; i += nt) { g_h[i] = h0[i]; g_c[i] = c0[i]; }
    for (int i = tid; i < BATCH * EDIM; i += nt) {
        int b = i >> 6, e = i & 63;
        g_decin[i] = b_se[e] + last_pos_rel[b * 2] * W_se[e] + last_pos_rel[b * 2 + 1] * W_se[EDIM + e];
    }
    for (int i = tid; i < 2 * P1D; i += nt) {
        int d = i >> 9, t = i & 511;
        float a = 0.f;
        for (int e = 0; e < EDIM; e++) a += W_pse[d * EDIM + e] * W_p1[e * P1D + t];
        g_M2[i] = a;
    }
    for (int i = tid; i < P1D; i += nt) {
        float a = b_p1[i];
        for (int e = 0; e < EDIM; e++) a += b_pse[e] * W_p1[e * P1D + i];
        g_cb[i] = a;
    }
}

// ---------------- fused LSTM step + hidden2pos + pos update + next dec_in ----------------
__global__ __launch_bounds__(512) void lstm_kernel(
    const float* __restrict__ W_ih, const float* __restrict__ b_ih,
    const float* __restrict__ W_hh, const float* __restrict__ b_hh,
    const float* __restrict__ W_hp, const float* __restrict__ b_hp,
    const float* __restrict__ W_se, const float* __restrict__ b_se,
    float* __restrict__ pred_out) {
    __shared__ float s_x[16 * EDIM];
    __shared__ float s_h[16 * HDIM];
    __shared__ float s_g[16 * G4];
    __shared__ float s_rel[32];
    int tid = threadIdx.x;
    int row0 = blockIdx.x * 16;
    for (int i = tid; i < 16 * EDIM; i += 512) s_x[i] = g_decin[row0 * EDIM + i];
    for (int i = tid; i < 16 * HDIM; i += 512) s_h[i] = g_h[row0 * HDIM + i];
    __syncthreads();
    {
        float acc[16];
        float bb = b_ih[tid] + b_hh[tid];
#pragma unroll
        for (int r = 0; r < 16; r++) acc[r] = bb;
        for (int k = 0; k < EDIM; k++) {
            float w = W_ih[k * G4 + tid];
#pragma unroll
            for (int r = 0; r < 16; r++) acc[r] += w * s_x[r * EDIM + k];
        }
        for (int k = 0; k < HDIM; k++) {
            float w = W_hh[k * G4 + tid];
#pragma unroll
            for (int r = 0; r < 16; r++) acc[r] += w * s_h[r * HDIM + k];
        }
#pragma unroll
        for (int r = 0; r < 16; r++) s_g[r * G4 + tid] = acc[r];
    }
    __syncthreads();
    for (int i = tid; i < 16 * HDIM; i += 512) {
        int r = i >> 7, hc = i & 127;
        const float* gr = s_g + r * G4;
        float ig = sigf(gr[hc]);
        float fg = sigf(gr[HDIM + hc]);
        float gg = tanhf(gr[2 * HDIM + hc]);
        float og = sigf(gr[3 * HDIM + hc]);
        float c = fg * g_c[(row0 + r) * HDIM + hc] + ig * gg;
        float hn = og * tanhf(c);
        g_c[(row0 + r) * HDIM + hc] = c;
        g_hmid[(row0 + r) * HDIM + hc] = hn;
        s_h[r * HDIM + hc] = hn;
    }
    __syncthreads();
    if (tid < 32) {
        int r = tid >> 1, d = tid & 1;
        float a = b_hp[d];
        for (int k = 0; k < HDIM; k++) a += s_h[r * HDIM + k] * W_hp[k * 2 + d];
        s_rel[tid] = a;
        pred_out[row0 * 2 + tid] = a;
        g_pos[row0 * 2 + tid] = a + g_pos[row0 * 2 + tid];
    }
    __syncthreads();
    for (int i = tid; i < 16 * EDIM; i += 512) {
        int r = i >> 6, e = i & 63;
        g_decin[(row0 + r) * EDIM + e] =
            b_se[e] + s_rel[r * 2] * W_se[e] + s_rel[r * 2 + 1] * W_se[EDIM + e];
    }
}

// ---------------- per-j term: hterm[j] = h_new[j] @ W_p1[64:192] + cb ----------------
__global__ __launch_bounds__(512) void hterm_kernel(const float* __restrict__ W_p1) {
    __shared__ float s_h[16 * HDIM];
    int tid = threadIdx.x;
    int row0 = blockIdx.x * 16;
    for (int i = tid; i < 16 * HDIM; i += 512) s_h[i] = g_hmid[row0 * HDIM + i];
    __syncthreads();
    float acc[16];
    float cb = g_cb[tid];
#pragma unroll
    for (int r = 0; r < 16; r++) acc[r] = cb;
    for (int k = 0; k < HDIM; k++) {
        float w = W_p1[(EDIM + k) * P1D + tid];
#pragma unroll
        for (int r = 0; r < 16; r++) acc[r] += w * s_h[r * HDIM + k];
    }
#pragma unroll
    for (int r = 0; r < 16; r++) g_hterm[(row0 + r) * P1D + tid] = acc[r];
}

// ---------------- layer1: y[s,i,j,:] = relu(hterm[j] + dx*M2[0] + dy*M2[1]) ----------------
__global__ __launch_bounds__(512) void layer1_kernel() {
    int s = blockIdx.x / NP, i = blockIdx.x % NP;
    int tid = threadIdx.x;
    __shared__ float sdx[NP], sdy[NP];
    if (tid < NP) {
        float xi = g_pos[(s * NP + i) * 2], yi = g_pos[(s * NP + i) * 2 + 1];
        sdx[tid] = g_pos[(s * NP + tid) * 2] - xi;
        sdy[tid] = g_pos[(s * NP + tid) * 2 + 1] - yi;
    }
    float m0 = g_M2[tid], m1 = g_M2[P1D + tid];
    __syncthreads();
    float* yout = g_y + (size_t)blockIdx.x * NP * P1D;
#pragma unroll
    for (int j = 0; j < NP; j++) {
        float v = g_hterm[(s * NP + j) * P1D + tid] + sdx[j] * m0 + sdy[j] * m1;
        yout[j * P1D + tid] = fmaxf(v, 0.f);
    }
}

// ---------------- dominant GEMM (18432x512 @ 512x1024) fused with relu+max-pool over j ----
// block: scene s (z), i-group of 4 (y), 128-wide n tile (x). M=96 rows (4 i x 24 j).
// f32x2 packed FMA micro-tile 6x8 per thread (256 threads, 16x16).
__global__ __launch_bounds__(256) void gemm_pool_kernel(const float* __restrict__ Wp2,
                                                        const float* __restrict__ bp2) {
    const int s = blockIdx.z, ig = blockIdx.y, n0 = blockIdx.x * 128;
    const int tid = threadIdx.x;
    const int tx = tid & 15, ty = tid >> 4;
    const float* A = g_y + (size_t)(s * 576 + ig * 96) * P1D;
    __shared__ float As[96][KC + 1];
    __shared__ float Bs[KC][128];
    __shared__ float Red[16][128];
    u64 acc[6][4];
#pragma unroll
    for (int mm = 0; mm < 6; mm++)
#pragma unroll
        for (int q = 0; q < 4; q++) acc[mm][q] = 0ull;

    for (int kc = 0; kc < P1D; kc += KC) {
#pragma unroll
        for (int p = 0; p < 6; p++) {
            int idx = tid + p * 256;
            int m = idx >> 4, kk = idx & 15;
            As[m][kk] = A[(size_t)m * P1D + kc + kk];
        }
#pragma unroll
        for (int p = 0; p < 8; p++) {
            int idx = tid + p * 256;
            int kk = idx >> 7, nn = idx & 127;
            Bs[kk][nn] = Wp2[(size_t)(kc + kk) * BNK + n0 + nn];
        }
        __syncthreads();
#pragma unroll
        for (int kk = 0; kk < KC; kk++) {
            u64 b0, b1, b2, b3;
            const u64* bp = (const u64*)&Bs[kk][tx * 8];
            b0 = bp[0]; b1 = bp[1]; b2 = bp[2]; b3 = bp[3];
#pragma unroll
            for (int mm = 0; mm < 6; mm++) {
                u64 a2 = pack2(As[ty * 6 + mm][kk]);
                acc[mm][0] = ffma2(a2, b0, acc[mm][0]);
                acc[mm][1] = ffma2(a2, b1, acc[mm][1]);
                acc[mm][2] = ffma2(a2, b2, acc[mm][2]);
                acc[mm][3] = ffma2(a2, b3, acc[mm][3]);
            }
        }
        __syncthreads();
    }
    // bias + relu + max over this thread's 6 rows (all same i since 6 | 24)
    float bias[8];
#pragma unroll
    for (int nn = 0; nn < 8; nn++) bias[nn] = bp2[n0 + tx * 8 + nn];
    float pmax[8];
#pragma unroll
    for (int nn = 0; nn < 8; nn++) pmax[nn] = 0.f;  // relu floor
#pragma unroll
    for (int mm = 0; mm < 6; mm++) {
#pragma unroll
        for (int q = 0; q < 4; q++) {
            float lo, hi;
            unpack2(acc[mm][q], lo, hi);
            pmax[2 * q] = fmaxf(pmax[2 * q], lo + bias[2 * q]);
            pmax[2 * q + 1] = fmaxf(pmax[2 * q + 1], hi + bias[2 * q + 1]);
        }
    }
#pragma unroll
    for (int nn = 0; nn < 8; nn++) Red[ty][tx * 8 + nn] = pmax[nn];
    __syncthreads();
#pragma unroll
    for (int p = 0; p < 2; p++) {
        int idx = tid + p * 256;
        int il = idx >> 7, col = idx & 127;
        float m = fmaxf(fmaxf(Red[il * 4][col], Red[il * 4 + 1][col]),
                        fmaxf(Red[il * 4 + 2][col], Red[il * 4 + 3][col]));
        g_pool[(size_t)(s * NP + ig * 4 + il) * BNK + n0 + col] = m;
    }
}

// ---------------- decoder MLP layer 1: relu([h_new|pool] @ W_m1 + b_m1) ----------------
__global__ __launch_bounds__(256) void mlp1_kernel(const float* __restrict__ Wm1,
                                                   const float* __restrict__ bm1) {
    const int m0 = blockIdx.y * 64, n0 = blockIdx.x * 128;
    const int tid = threadIdx.x, tx = tid & 15, ty = tid >> 4;
    __shared__ float As[64][KC + 1];
    __shared__ float Bs[KC][128];
    float acc[4][8];
#pragma unroll
    for (int mm = 0; mm < 4; mm++)
#pragma unroll
        for (int nn = 0; nn < 8; nn++) acc[mm][nn] = 0.f;

    for (int kc = 0; kc < HDIM + BNK; kc += KC) {
#pragma unroll
        for (int p = 0; p < 4; p++) {
            int idx = tid + p * 256;
            int m = idx >> 4, kk = idx & 15;
            float v;
            if (kc < HDIM) v = g_hmid[(size_t)(m0 + m) * HDIM + kc + kk];
            else v = g_pool[(size_t)(m0 + m) * BNK + (kc - HDIM) + kk];
            As[m][kk] = v;
        }
#pragma unroll
        for (int p = 0; p < 8; p++) {
            int idx = tid + p * 256;
            int kk = idx >> 7, nn = idx & 127;
            Bs[kk][nn] = Wm1[(size_t)(kc + kk) * MLPD + n0 + nn];
        }
        __syncthreads();
#pragma unroll
        for (int kk = 0; kk < KC; kk++) {
            float a[4];
#pragma unroll
            for (int mm = 0; mm < 4; mm++) a[mm] = As[ty * 4 + mm][kk];
            float4 b0 = *(const float4*)&Bs[kk][tx * 8];
            float4 b1 = *(const float4*)&Bs[kk][tx * 8 + 4];
#pragma unroll
            for (int mm = 0; mm < 4; mm++) {
                acc[mm][0] += a[mm] * b0.x; acc[mm][1] += a[mm] * b0.y;
                acc[mm][2] += a[mm] * b0.z; acc[mm][3] += a[mm] * b0.w;
                acc[mm][4] += a[mm] * b1.x; acc[mm][5] += a[mm] * b1.y;
                acc[mm][6] += a[mm] * b1.z; acc[mm][7] += a[mm] * b1.w;
            }
        }
        __syncthreads();
    }
#pragma unroll
    for (int mm = 0; mm < 4; mm++)
#pragma unroll
        for (int nn = 0; nn < 8; nn++) {
            int n = n0 + tx * 8 + nn;
            g_dh[(size_t)(m0 + ty * 4 + mm) * MLPD + n] = fmaxf(acc[mm][nn] + bm1[n], 0.f);
        }
}

// ---------------- decoder MLP layer 2: h = relu(dh @ W_m2 + b_m2) ----------------
__global__ __launch_bounds__(256) void mlp2_kernel(const float* __restrict__ Wm2,
                                                   const float* __restrict__ bm2) {
    const int m0 = blockIdx.x * 32;
    const int tid = threadIdx.x, tx = tid & 15, ty = tid >> 4;
    __shared__ float As[32][KC + 1];
    __shared__ float Bs[KC][128];
    float acc[2][8];
#pragma unroll
    for (int mm = 0; mm < 2; mm++)
#pragma unroll
        for (int nn = 0; nn < 8; nn++) acc[mm][nn] = 0.f;

    for (int kc = 0; kc < MLPD; kc += KC) {
#pragma unroll
        for (int p = 0; p < 2; p++) {
            int idx = tid + p * 256;
            int m = idx >> 4, kk = idx & 15;
            As[m][kk] = g_dh[(size_t)(m0 + m) * MLPD + kc + kk];
        }
#pragma unroll
        for (int p = 0; p < 8; p++) {
            int idx = tid + p * 256;
            int kk = idx >> 7, nn = idx & 127;
            Bs[kk][nn] = Wm2[(size_t)(kc + kk) * HDIM + nn];
        }
        __syncthreads();
#pragma unroll
        for (int kk = 0; kk < KC; kk++) {
            float a[2];
            a[0] = As[ty * 2][kk];
            a[1] = As[ty * 2 + 1][kk];
            float4 b0 = *(const float4*)&Bs[kk][tx * 8];
            float4 b1 = *(const float4*)&Bs[kk][tx * 8 + 4];
#pragma unroll
            for (int mm = 0; mm < 2; mm++) {
                acc[mm][0] += a[mm] * b0.x; acc[mm][1] += a[mm] * b0.y;
                acc[mm][2] += a[mm] * b0.z; acc[mm][3] += a[mm] * b0.w;
                acc[mm][4] += a[mm] * b1.x; acc[mm][5] += a[mm] * b1.y;
                acc[mm][6] += a[mm] * b1.z; acc[mm][7] += a[mm] * b1.w;
            }
        }
        __syncthreads();
    }
#pragma unroll
    for (int mm = 0; mm < 2; mm++)
#pragma unroll
        for (int nn = 0; nn < 8; nn++) {
            int n = tx * 8 + nn;
            g_h[(size_t)(m0 + ty * 2 + mm) * HDIM + n] = fmaxf(acc[mm][nn] + bm2[n], 0.f);
        }
}

__global__ void copy_h_kernel(float* __restrict__ out) {
    int i = blockIdx.x * blockDim.x + threadIdx.x;
    if (i < BATCH * HDIM) out[i] = g_h[i];
}

// ---------------- launch ----------------
extern "C" void kernel_launch(void* const* d_in, const int* in_sizes, int n_in,
                              void* d_out, int out_size) {
    const float* last_pos     = (const float*)d_in[0];
    const float* last_pos_rel = (const float*)d_in[1];
    const float* h0   = (const float*)d_in[2];
    const float* c0   = (const float*)d_in[3];
    /* d_in[4] = seq_start_end (uniform scenes; unused) */
    const float* W_se = (const float*)d_in[5];
    const float* b_se = (const float*)d_in[6];
    const float* W_ih = (const float*)d_in[7];
    const float* b_ih = (const float*)d_in[8];
    const float* W_hh = (const float*)d_in[9];
    const float* b_hh = (const float*)d_in[10];
    const float* W_hp = (const float*)d_in[11];
    const float* b_hp = (const float*)d_in[12];
    const float* W_pse = (const float*)d_in[13];
    const float* b_pse = (const float*)d_in[14];
    const float* W_p1 = (const float*)d_in[15];
    const float* b_p1 = (const float*)d_in[16];
    const float* W_p2 = (const float*)d_in[17];
    const float* b_p2 = (const float*)d_in[18];
    const float* W_m1 = (const float*)d_in[19];
    const float* b_m1 = (const float*)d_in[20];
    const float* W_m2 = (const float*)d_in[21];
    const float* b_m2 = (const float*)d_in[22];
    float* out = (float*)d_out;

    setup_kernel<<<96, 256>>>(last_pos, last_pos_rel, h0, c0, W_se, b_se, W_pse, b_pse, W_p1, b_p1);
    for (int t = 0; t < TSTEPS; t++) {
        lstm_kernel<<<BATCH / 16, 512>>>(W_ih, b_ih, W_hh, b_hh, W_hp, b_hp, W_se, b_se,
                                         out + (size_t)t * BATCH * 2);
        hterm_kernel<<<BATCH / 16, 512>>>(W_p1);
        layer1_kernel<<<BATCH, 512>>>();
        gemm_pool_kernel<<<dim3(8, 6, 32), 256>>>(W_p2, b_p2);
        mlp1_kernel<<<dim3(8, 12), 256>>>(W_m1, b_m1);
        mlp2_kernel<<<24, 256>>>(W_m2, b_m2);
    }
    copy_h_kernel<<<(BATCH * HDIM + 255) / 256, 256>>>(out + TSTEPS * BATCH * 2);
}

// round 3
// speedup vs baseline: 1.7763x; 1.7763x over previous
#include <cuda_runtime.h>
#include <math.h>
#include <stdint.h>

#define BATCH 768
#define NS 32
#define NP 24
#define EDIM 64
#define HDIM 128
#define G4 512      // 4*HDIM
#define P1D 512     // pool hidden
#define BNK 1024
#define MLPD 1024
#define TSTEPS 12
#define KC 16

// ---------------- scratch (static device memory; no allocations) ----------------
__device__ float g_pos[BATCH * 2];
__device__ float g_decin[BATCH * EDIM];
__device__ float g_h[BATCH * HDIM];
__device__ float g_c[BATCH * HDIM];
__device__ float g_hmid[BATCH * HDIM];
__device__ float g_hterm[BATCH * P1D];
__device__ float g_y[(size_t)BATCH * NP * P1D];   // tf32 bits
__device__ float g_pool[(size_t)BATCH * BNK];
__device__ float g_dh[(size_t)BATCH * MLPD];
__device__ float g_M2[2 * P1D];
__device__ float g_cb[P1D];
__device__ float g_Wp2t[(size_t)BNK * P1D];       // W_p2 transposed, tf32 bits

__device__ __forceinline__ float sigf(float x) { return 1.f / (1.f + expf(-x)); }

__device__ __forceinline__ uint32_t f2tf32(float v) {
    uint32_t r;
    asm("cvt.rna.tf32.f32 %0, %1;" : "=r"(r) : "f"(v));
    return r;
}

// warp-level tf32 HMMA (generic PTX, sm_80+; compiles on compute_103)
__device__ __forceinline__ void mma_tf32(float* d, const uint32_t* a, const uint32_t* b) {
    asm volatile(
        "mma.sync.aligned.m16n8k8.row.col.f32.tf32.tf32.f32 "
        "{%0,%1,%2,%3}, {%4,%5,%6,%7}, {%8,%9}, {%0,%1,%2,%3};"
        : "+f"(d[0]), "+f"(d[1]), "+f"(d[2]), "+f"(d[3])
        : "r"(a[0]), "r"(a[1]), "r"(a[2]), "r"(a[3]), "r"(b[0]), "r"(b[1]));
}

// ---------------- setup: init state, fold W_pse@W_p1a, initial dec_in, W_p2^T ---------
__global__ void setup_kernel(const float* __restrict__ last_pos,
                             const float* __restrict__ last_pos_rel,
                             const float* __restrict__ h0, const float* __restrict__ c0,
                             const float* __restrict__ W_se, const float* __restrict__ b_se,
                             const float* __restrict__ W_pse, const float* __restrict__ b_pse,
                             const float* __restrict__ W_p1, const float* __restrict__ b_p1,
                             const float* __restrict__ W_p2) {
    int tid = blockIdx.x * blockDim.x + threadIdx.x;
    int nt = gridDim.x * blockDim.x;
    for (int i = tid; i < BATCH * 2; i += nt) g_pos[i] = last_pos[i];
    for (int i = tid; i < BATCH * HDIM; i += nt) { g_h[i] = h0[i]; g_c[i] = c0[i]; }
    for (int i = tid; i < BATCH * EDIM; i += nt) {
        int b = i >> 6, e = i & 63;
        g_decin[i] = b_se[e] + last_pos_rel[b * 2] * W_se[e] + last_pos_rel[b * 2 + 1] * W_se[EDIM + e];
    }
    for (int i = tid; i < 2 * P1D; i += nt) {
        int d = i >> 9, t = i & 511;
        float a = 0.f;
        for (int e = 0; e < EDIM; e++) a += W_pse[d * EDIM + e] * W_p1[e * P1D + t];
        g_M2[i] = a;
    }
    for (int i = tid; i < P1D; i += nt) {
        float a = b_p1[i];
        for (int e = 0; e < EDIM; e++) a += b_pse[e] * W_p1[e * P1D + i];
        g_cb[i] = a;
    }
    // transpose W_p2 [512,1024] -> [1024,512], tf32-rounded
    uint32_t* wt = (uint32_t*)g_Wp2t;
    for (int i = tid; i < BNK * P1D; i += nt) {
        int n = i / P1D, k = i % P1D;
        wt[i] = f2tf32(W_p2[(size_t)k * BNK + n]);
    }
}

// ---------------- fused LSTM step + hidden2pos + pos update + next dec_in ----------------
__global__ __launch_bounds__(512) void lstm_kernel(
    const float* __restrict__ W_ih, const float* __restrict__ b_ih,
    const float* __restrict__ W_hh, const float* __restrict__ b_hh,
    const float* __restrict__ W_hp, const float* __restrict__ b_hp,
    const float* __restrict__ W_se, const float* __restrict__ b_se,
    float* __restrict__ pred_out) {
    __shared__ float s_x[16 * EDIM];
    __shared__ float s_h[16 * HDIM];
    __shared__ float s_g[16 * G4];
    __shared__ float s_rel[32];
    int tid = threadIdx.x;
    int row0 = blockIdx.x * 16;
    for (int i = tid; i < 16 * EDIM; i += 512) s_x[i] = g_decin[row0 * EDIM + i];
    for (int i = tid; i < 16 * HDIM; i += 512) s_h[i] = g_h[row0 * HDIM + i];
    __syncthreads();
    {
        float acc[16];
        float bb = b_ih[tid] + b_hh[tid];
#pragma unroll
        for (int r = 0; r < 16; r++) acc[r] = bb;
        for (int k = 0; k < EDIM; k++) {
            float w = W_ih[k * G4 + tid];
#pragma unroll
            for (int r = 0; r < 16; r++) acc[r] += w * s_x[r * EDIM + k];
        }
        for (int k = 0; k < HDIM; k++) {
            float w = W_hh[k * G4 + tid];
#pragma unroll
            for (int r = 0; r < 16; r++) acc[r] += w * s_h[r * HDIM + k];
        }
#pragma unroll
        for (int r = 0; r < 16; r++) s_g[r * G4 + tid] = acc[r];
    }
    __syncthreads();
    for (int i = tid; i < 16 * HDIM; i += 512) {
        int r = i >> 7, hc = i & 127;
        const float* gr = s_g + r * G4;
        float ig = sigf(gr[hc]);
        float fg = sigf(gr[HDIM + hc]);
        float gg = tanhf(gr[2 * HDIM + hc]);
        float og = sigf(gr[3 * HDIM + hc]);
        float c = fg * g_c[(row0 + r) * HDIM + hc] + ig * gg;
        float hn = og * tanhf(c);
        g_c[(row0 + r) * HDIM + hc] = c;
        g_hmid[(row0 + r) * HDIM + hc] = hn;
        s_h[r * HDIM + hc] = hn;
    }
    __syncthreads();
    if (tid < 32) {
        int r = tid >> 1, d = tid & 1;
        float a = b_hp[d];
        for (int k = 0; k < HDIM; k++) a += s_h[r * HDIM + k] * W_hp[k * 2 + d];
        s_rel[tid] = a;
        pred_out[row0 * 2 + tid] = a;
        g_pos[row0 * 2 + tid] = a + g_pos[row0 * 2 + tid];
    }
    __syncthreads();
    for (int i = tid; i < 16 * EDIM; i += 512) {
        int r = i >> 6, e = i & 63;
        g_decin[(row0 + r) * EDIM + e] =
            b_se[e] + s_rel[r * 2] * W_se[e] + s_rel[r * 2 + 1] * W_se[EDIM + e];
    }
}

// ---------------- per-j term: hterm[j] = h_new[j] @ W_p1[64:192] + cb ----------------
__global__ __launch_bounds__(512) void hterm_kernel(const float* __restrict__ W_p1) {
    __shared__ float s_h[16 * HDIM];
    int tid = threadIdx.x;
    int row0 = blockIdx.x * 16;
    for (int i = tid; i < 16 * HDIM; i += 512) s_h[i] = g_hmid[row0 * HDIM + i];
    __syncthreads();
    float acc[16];
    float cb = g_cb[tid];
#pragma unroll
    for (int r = 0; r < 16; r++) acc[r] = cb;
    for (int k = 0; k < HDIM; k++) {
        float w = W_p1[(EDIM + k) * P1D + tid];
#pragma unroll
        for (int r = 0; r < 16; r++) acc[r] += w * s_h[r * HDIM + k];
    }
#pragma unroll
    for (int r = 0; r < 16; r++) g_hterm[(row0 + r) * P1D + tid] = acc[r];
}

// ---------------- layer1: y[s,i,j,:] = tf32(relu(hterm[j] + dx*M2[0] + dy*M2[1])) -------
// also zeroes g_pool for this (s,i) row (atomicMax target in the GEMM epilogue)
__global__ __launch_bounds__(512) void layer1_kernel() {
    int s = blockIdx.x / NP, i = blockIdx.x % NP;
    int tid = threadIdx.x;
    __shared__ float sdx[NP], sdy[NP];
    if (tid < NP) {
        float xi = g_pos[(s * NP + i) * 2], yi = g_pos[(s * NP + i) * 2 + 1];
        sdx[tid] = g_pos[(s * NP + tid) * 2] - xi;
        sdy[tid] = g_pos[(s * NP + tid) * 2 + 1] - yi;
    }
    g_pool[(size_t)blockIdx.x * BNK + tid] = 0.f;
    g_pool[(size_t)blockIdx.x * BNK + P1D + tid] = 0.f;
    float m0 = g_M2[tid], m1 = g_M2[P1D + tid];
    __syncthreads();
    uint32_t* yout = (uint32_t*)(g_y + (size_t)blockIdx.x * NP * P1D);
#pragma unroll
    for (int j = 0; j < NP; j++) {
        float v = g_hterm[(s * NP + j) * P1D + tid] + sdx[j] * m0 + sdy[j] * m1;
        yout[j * P1D + tid] = f2tf32(fmaxf(v, 0.f));
    }
}

// ---------------- dominant GEMM via mma.sync tf32, fused bias+relu+max-pool -------------
// CTA tile M=128 x N=128, K=512 in 16 chunks of 32. 8 warps, warp tile 64x32.
#define GP_KC 32
#define APAD 36
#define DPAD 132

__global__ __launch_bounds__(256) void gemm_pool_mma(const float* __restrict__ bp2) {
    extern __shared__ char smem[];
    float* As = (float*)smem;                 // [128][APAD]
    float* Bs = As + 128 * APAD;              // [128][APAD]
    float* Dsm = (float*)smem;                // [128][DPAD] overlay (post-mainloop)
    const uint32_t* Au = (const uint32_t*)As;
    const uint32_t* Bu = (const uint32_t*)Bs;

    const int tid = threadIdx.x;
    const int wid = tid >> 5, lane = tid & 31;
    const int gid = lane >> 2, tig = lane & 3;
    const int wm = (wid & 1) * 64, wn = (wid >> 1) * 32;
    const int n0 = blockIdx.x * 128, R0 = blockIdx.y * 128;
    const float* Ag = g_y + (size_t)R0 * P1D;
    const float* Bg = g_Wp2t + (size_t)n0 * P1D;

    float acc[4][4][4] = {};

    for (int kc = 0; kc < P1D; kc += GP_KC) {
        __syncthreads();
#pragma unroll
        for (int p = 0; p < 2; p++) {
            int idx = tid + p * 256;
            int row = idx >> 2, ks = (idx & 3) * 8;
            const float4* srca = (const float4*)(Ag + (size_t)row * P1D + kc + ks);
            float4 a0 = srca[0], a1 = srca[1];
            float* da = As + row * APAD + ks;
            ((float2*)da)[0] = make_float2(a0.x, a0.y);
            ((float2*)da)[1] = make_float2(a0.z, a0.w);
            ((float2*)da)[2] = make_float2(a1.x, a1.y);
            ((float2*)da)[3] = make_float2(a1.z, a1.w);
            const float4* srcb = (const float4*)(Bg + (size_t)row * P1D + kc + ks);
            float4 b0 = srcb[0], b1 = srcb[1];
            float* db = Bs + row * APAD + ks;
            ((float2*)db)[0] = make_float2(b0.x, b0.y);
            ((float2*)db)[1] = make_float2(b0.z, b0.w);
            ((float2*)db)[2] = make_float2(b1.x, b1.y);
            ((float2*)db)[3] = make_float2(b1.z, b1.w);
        }
        __syncthreads();
#pragma unroll
        for (int kk = 0; kk < GP_KC; kk += 8) {
            uint32_t af[4][4], bf[4][2];
#pragma unroll
            for (int mi = 0; mi < 4; mi++) {
                int r = wm + mi * 16 + gid;
                af[mi][0] = Au[r * APAD + kk + tig];
                af[mi][1] = Au[(r + 8) * APAD + kk + tig];
                af[mi][2] = Au[r * APAD + kk + tig + 4];
                af[mi][3] = Au[(r + 8) * APAD + kk + tig + 4];
            }
#pragma unroll
            for (int ni = 0; ni < 4; ni++) {
                int n = wn + ni * 8 + gid;
                bf[ni][0] = Bu[n * APAD + kk + tig];
                bf[ni][1] = Bu[n * APAD + kk + tig + 4];
            }
#pragma unroll
            for (int mi = 0; mi < 4; mi++)
#pragma unroll
                for (int ni = 0; ni < 4; ni++)
                    mma_tf32(acc[mi][ni], af[mi], bf[ni]);
        }
    }
    __syncthreads();

    // ---- epilogue: bias + relu into smem, per-ped max over 24 rows, atomicMax ----
#pragma unroll
    for (int mi = 0; mi < 4; mi++)
#pragma unroll
        for (int ni = 0; ni < 4; ni++) {
            int r = wm + mi * 16 + gid;
            int c = wn + ni * 8 + 2 * tig;
            float bv0 = bp2[n0 + c], bv1 = bp2[n0 + c + 1];
            Dsm[r * DPAD + c]           = fmaxf(acc[mi][ni][0] + bv0, 0.f);
            Dsm[r * DPAD + c + 1]       = fmaxf(acc[mi][ni][1] + bv1, 0.f);
            Dsm[(r + 8) * DPAD + c]     = fmaxf(acc[mi][ni][2] + bv0, 0.f);
            Dsm[(r + 8) * DPAD + c + 1] = fmaxf(acc[mi][ni][3] + bv1, 0.f);
        }
    __syncthreads();
    const int ped0 = R0 / NP;
    const int pedN = (R0 + 127) / NP - ped0 + 1;   // <= 6
    for (int it = tid; it < pedN * 128; it += 256) {
        int pl = it >> 7, c = it & 127;
        int gp = ped0 + pl;
        int rs = gp * NP - R0, re = rs + NP;
        if (rs < 0) rs = 0;
        if (re > 128) re = 128;
        float v = 0.f;
        for (int rr = rs; rr < re; rr++) v = fmaxf(v, Dsm[rr * DPAD + c]);
        atomicMax((int*)&g_pool[(size_t)gp * BNK + n0 + c], __float_as_int(v));
    }
}

// ---------------- decoder MLP layer 1: relu([h_new|pool] @ W_m1 + b_m1) ----------------
__global__ __launch_bounds__(256) void mlp1_kernel(const float* __restrict__ Wm1,
                                                   const float* __restrict__ bm1) {
    const int m0 = blockIdx.y * 64, n0 = blockIdx.x * 128;
    const int tid = threadIdx.x, tx = tid & 15, ty = tid >> 4;
    __shared__ float As[64][KC + 1];
    __shared__ float Bs[KC][128];
    float acc[4][8];
#pragma unroll
    for (int mm = 0; mm < 4; mm++)
#pragma unroll
        for (int nn = 0; nn < 8; nn++) acc[mm][nn] = 0.f;

    for (int kc = 0; kc < HDIM + BNK; kc += KC) {
#pragma unroll
        for (int p = 0; p < 4; p++) {
            int idx = tid + p * 256;
            int m = idx >> 4, kk = idx & 15;
            float v;
            if (kc < HDIM) v = g_hmid[(size_t)(m0 + m) * HDIM + kc + kk];
            else v = g_pool[(size_t)(m0 + m) * BNK + (kc - HDIM) + kk];
            As[m][kk] = v;
        }
#pragma unroll
        for (int p = 0; p < 8; p++) {
            int idx = tid + p * 256;
            int kk = idx >> 7, nn = idx & 127;
            Bs[kk][nn] = Wm1[(size_t)(kc + kk) * MLPD + n0 + nn];
        }
        __syncthreads();
#pragma unroll
        for (int kk = 0; kk < KC; kk++) {
            float a[4];
#pragma unroll
            for (int mm = 0; mm < 4; mm++) a[mm] = As[ty * 4 + mm][kk];
            float4 b0 = *(const float4*)&Bs[kk][tx * 8];
            float4 b1 = *(const float4*)&Bs[kk][tx * 8 + 4];
#pragma unroll
            for (int mm = 0; mm < 4; mm++) {
                acc[mm][0] += a[mm] * b0.x; acc[mm][1] += a[mm] * b0.y;
                acc[mm][2] += a[mm] * b0.z; acc[mm][3] += a[mm] * b0.w;
                acc[mm][4] += a[mm] * b1.x; acc[mm][5] += a[mm] * b1.y;
                acc[mm][6] += a[mm] * b1.z; acc[mm][7] += a[mm] * b1.w;
            }
        }
        __syncthreads();
    }
#pragma unroll
    for (int mm = 0; mm < 4; mm++)
#pragma unroll
        for (int nn = 0; nn < 8; nn++) {
            int n = n0 + tx * 8 + nn;
            g_dh[(size_t)(m0 + ty * 4 + mm) * MLPD + n] = fmaxf(acc[mm][nn] + bm1[n], 0.f);
        }
}

// ---------------- decoder MLP layer 2: h = relu(dh @ W_m2 + b_m2) ----------------
__global__ __launch_bounds__(256) void mlp2_kernel(const float* __restrict__ Wm2,
                                                   const float* __restrict__ bm2) {
    const int m0 = blockIdx.x * 32;
    const int tid = threadIdx.x, tx = tid & 15, ty = tid >> 4;
    __shared__ float As[32][KC + 1];
    __shared__ float Bs[KC][128];
    float acc[2][8];
#pragma unroll
    for (int mm = 0; mm < 2; mm++)
#pragma unroll
        for (int nn = 0; nn < 8; nn++) acc[mm][nn] = 0.f;

    for (int kc = 0; kc < MLPD; kc += KC) {
#pragma unroll
        for (int p = 0; p < 2; p++) {
            int idx = tid + p * 256;
            int m = idx >> 4, kk = idx & 15;
            As[m][kk] = g_dh[(size_t)(m0 + m) * MLPD + kc + kk];
        }
#pragma unroll
        for (int p = 0; p < 8; p++) {
            int idx = tid + p * 256;
            int kk = idx >> 7, nn = idx & 127;
            Bs[kk][nn] = Wm2[(size_t)(kc + kk) * HDIM + nn];
        }
        __syncthreads();
#pragma unroll
        for (int kk = 0; kk < KC; kk++) {
            float a[2];
            a[0] = As[ty * 2][kk];
            a[1] = As[ty * 2 + 1][kk];
            float4 b0 = *(const float4*)&Bs[kk][tx * 8];
            float4 b1 = *(const float4*)&Bs[kk][tx * 8 + 4];
#pragma unroll
            for (int mm = 0; mm < 2; mm++) {
                acc[mm][0] += a[mm] * b0.x; acc[mm][1] += a[mm] * b0.y;
                acc[mm][2] += a[mm] * b0.z; acc[mm][3] += a[mm] * b0.w;
                acc[mm][4] += a[mm] * b1.x; acc[mm][5] += a[mm] * b1.y;
                acc[mm][6] += a[mm] * b1.z; acc[mm][7] += a[mm] * b1.w;
            }
        }
        __syncthreads();
    }
#pragma unroll
    for (int mm = 0; mm < 2; mm++)
#pragma unroll
        for (int nn = 0; nn < 8; nn++) {
            int n = tx * 8 + nn;
            g_h[(size_t)(m0 + ty * 2 + mm) * HDIM + n] = fmaxf(acc[mm][nn] + bm2[n], 0.f);
        }
}

__global__ void copy_h_kernel(float* __restrict__ out) {
    int i = blockIdx.x * blockDim.x + threadIdx.x;
    if (i < BATCH * HDIM) out[i] = g_h[i];
}

// ---------------- launch ----------------
#define SMEM_GP (128 * DPAD * 4)   // 67584 bytes (covers As+Bs too)

extern "C" void kernel_launch(void* const* d_in, const int* in_sizes, int n_in,
                              void* d_out, int out_size) {
    const float* last_pos     = (const float*)d_in[0];
    const float* last_pos_rel = (const float*)d_in[1];
    const float* h0   = (const float*)d_in[2];
    const float* c0   = (const float*)d_in[3];
    /* d_in[4] = seq_start_end (uniform scenes; unused) */
    const float* W_se = (const float*)d_in[5];
    const float* b_se = (const float*)d_in[6];
    const float* W_ih = (const float*)d_in[7];
    const float* b_ih = (const float*)d_in[8];
    const float* W_hh = (const float*)d_in[9];
    const float* b_hh = (const float*)d_in[10];
    const float* W_hp = (const float*)d_in[11];
    const float* b_hp = (const float*)d_in[12];
    const float* W_pse = (const float*)d_in[13];
    const float* b_pse = (const float*)d_in[14];
    const float* W_p1 = (const float*)d_in[15];
    const float* b_p1 = (const float*)d_in[16];
    const float* W_p2 = (const float*)d_in[17];
    const float* b_p2 = (const float*)d_in[18];
    const float* W_m1 = (const float*)d_in[19];
    const float* b_m1 = (const float*)d_in[20];
    const float* W_m2 = (const float*)d_in[21];
    const float* b_m2 = (const float*)d_in[22];
    float* out = (float*)d_out;

    cudaFuncSetAttribute(gemm_pool_mma, cudaFuncAttributeMaxDynamicSharedMemorySize, SMEM_GP);

    setup_kernel<<<96, 256>>>(last_pos, last_pos_rel, h0, c0, W_se, b_se, W_pse, b_pse,
                              W_p1, b_p1, W_p2);
    for (int t = 0; t < TSTEPS; t++) {
        lstm_kernel<<<BATCH / 16, 512>>>(W_ih, b_ih, W_hh, b_hh, W_hp, b_hp, W_se, b_se,
                                         out + (size_t)t * BATCH * 2);
        hterm_kernel<<<BATCH / 16, 512>>>(W_p1);
        layer1_kernel<<<BATCH, 512>>>();
        gemm_pool_mma<<<dim3(BNK / 128, (BATCH * NP) / 128), 256, SMEM_GP>>>(b_p2);
        mlp1_kernel<<<dim3(8, 12), 256>>>(W_m1, b_m1);
        mlp2_kernel<<<24, 256>>>(W_m2, b_m2);
    }
    copy_h_kernel<<<(BATCH * HDIM + 255) / 256, 256>>>(out + TSTEPS * BATCH * 2);
}

// round 4
// speedup vs baseline: 2.5163x; 1.4166x over previous
#include <cuda_runtime.h>
#include <math.h>
#include <stdint.h>

#define BATCH 768
#define NS 32
#define NP 24
#define EDIM 64
#define HDIM 128
#define G4 512      // 4*HDIM
#define P1D 512     // pool hidden
#define BNK 1024
#define MLPD 1024
#define KTOT (HDIM + BNK)   // 1152
#define TSTEPS 12
#define KC 16

// ---------------- scratch (static device memory; no allocations) ----------------
__device__ float g_pos[BATCH * 2];
__device__ float g_decin[BATCH * EDIM];
__device__ float g_h[BATCH * HDIM];
__device__ float g_c[BATCH * HDIM];
__device__ float g_hmid[BATCH * HDIM];
__device__ float g_hterm[BATCH * P1D];
__device__ float g_y[(size_t)BATCH * NP * P1D];   // tf32 bits
__device__ float g_pool[(size_t)BATCH * BNK];
__device__ float g_dh[(size_t)BATCH * MLPD];
__device__ float g_M2[2 * P1D];
__device__ float g_cb[P1D];
__device__ float g_Wp2t[(size_t)BNK * P1D];       // W_p2^T, tf32 bits
__device__ float g_Wm1t[(size_t)MLPD * KTOT];     // W_m1^T, tf32 bits

__device__ __forceinline__ float sigf(float x) { return 1.f / (1.f + expf(-x)); }

__device__ __forceinline__ uint32_t f2tf32(float v) {
    uint32_t r;
    asm("cvt.rna.tf32.f32 %0, %1;" : "=r"(r) : "f"(v));
    return r;
}

// warp-level tf32 HMMA (generic PTX, sm_80+)
__device__ __forceinline__ void mma_tf32(float* d, const uint32_t* a, const uint32_t* b) {
    asm volatile(
        "mma.sync.aligned.m16n8k8.row.col.f32.tf32.tf32.f32 "
        "{%0,%1,%2,%3}, {%4,%5,%6,%7}, {%8,%9}, {%0,%1,%2,%3};"
        : "+f"(d[0]), "+f"(d[1]), "+f"(d[2]), "+f"(d[3])
        : "r"(a[0]), "r"(a[1]), "r"(a[2]), "r"(a[3]), "r"(b[0]), "r"(b[1]));
}

__device__ __forceinline__ uint32_t smem_u32(const void* p) {
    uint32_t a;
    asm("{ .reg .u64 t; cvta.to.shared.u64 t, %1; cvt.u32.u64 %0, t; }" : "=r"(a) : "l"(p));
    return a;
}
__device__ __forceinline__ void cp_async16(uint32_t saddr, const void* g) {
    asm volatile("cp.async.cg.shared.global [%0], [%1], 16;" :: "r"(saddr), "l"(g));
}
#define CP_COMMIT() asm volatile("cp.async.commit_group;" ::: "memory")
#define CP_WAIT(n)  asm volatile("cp.async.wait_group %0;" :: "n"(n) : "memory")

// ---------------- setup ----------------
__global__ void setup_kernel(const float* __restrict__ last_pos,
                             const float* __restrict__ last_pos_rel,
                             const float* __restrict__ h0, const float* __restrict__ c0,
                             const float* __restrict__ W_se, const float* __restrict__ b_se,
                             const float* __restrict__ W_pse, const float* __restrict__ b_pse,
                             const float* __restrict__ W_p1, const float* __restrict__ b_p1,
                             const float* __restrict__ W_p2, const float* __restrict__ W_m1) {
    int tid = blockIdx.x * blockDim.x + threadIdx.x;
    int nt = gridDim.x * blockDim.x;
    for (int i = tid; i < BATCH * 2; i += nt) g_pos[i] = last_pos[i];
    for (int i = tid; i < BATCH * HDIM; i += nt) { g_h[i] = h0[i]; g_c[i] = c0[i]; }
    for (int i = tid; i < BATCH * EDIM; i += nt) {
        int b = i >> 6, e = i & 63;
        g_decin[i] = b_se[e] + last_pos_rel[b * 2] * W_se[e] + last_pos_rel[b * 2 + 1] * W_se[EDIM + e];
    }
    for (int i = tid; i < 2 * P1D; i += nt) {
        int d = i >> 9, t = i & 511;
        float a = 0.f;
        for (int e = 0; e < EDIM; e++) a += W_pse[d * EDIM + e] * W_p1[e * P1D + t];
        g_M2[i] = a;
    }
    for (int i = tid; i < P1D; i += nt) {
        float a = b_p1[i];
        for (int e = 0; e < EDIM; e++) a += b_pse[e] * W_p1[e * P1D + i];
        g_cb[i] = a;
    }
    uint32_t* wt = (uint32_t*)g_Wp2t;
    for (int i = tid; i < BNK * P1D; i += nt) {
        int n = i / P1D, k = i % P1D;
        wt[i] = f2tf32(W_p2[(size_t)k * BNK + n]);
    }
    uint32_t* wm = (uint32_t*)g_Wm1t;
    for (int i = tid; i < MLPD * KTOT; i += nt) {
        int n = i / KTOT, k = i % KTOT;
        wm[i] = f2tf32(W_m1[(size_t)k * MLPD + n]);
    }
}

// ---------------- fused LSTM step + hidden2pos + pos update + next dec_in ----------------
__global__ __launch_bounds__(512) void lstm_kernel(
    const float* __restrict__ W_ih, const float* __restrict__ b_ih,
    const float* __restrict__ W_hh, const float* __restrict__ b_hh,
    const float* __restrict__ W_hp, const float* __restrict__ b_hp,
    const float* __restrict__ W_se, const float* __restrict__ b_se,
    float* __restrict__ pred_out) {
    __shared__ float s_x[16 * EDIM];
    __shared__ float s_h[16 * HDIM];
    __shared__ float s_g[16 * G4];
    __shared__ float s_rel[32];
    int tid = threadIdx.x;
    int row0 = blockIdx.x * 16;
    for (int i = tid; i < 16 * EDIM; i += 512) s_x[i] = g_decin[row0 * EDIM + i];
    for (int i = tid; i < 16 * HDIM; i += 512) s_h[i] = g_h[row0 * HDIM + i];
    __syncthreads();
    {
        float acc[16];
        float bb = b_ih[tid] + b_hh[tid];
#pragma unroll
        for (int r = 0; r < 16; r++) acc[r] = bb;
        for (int k = 0; k < EDIM; k++) {
            float w = W_ih[k * G4 + tid];
#pragma unroll
            for (int r = 0; r < 16; r++) acc[r] += w * s_x[r * EDIM + k];
        }
        for (int k = 0; k < HDIM; k++) {
            float w = W_hh[k * G4 + tid];
#pragma unroll
            for (int r = 0; r < 16; r++) acc[r] += w * s_h[r * HDIM + k];
        }
#pragma unroll
        for (int r = 0; r < 16; r++) s_g[r * G4 + tid] = acc[r];
    }
    __syncthreads();
    for (int i = tid; i < 16 * HDIM; i += 512) {
        int r = i >> 7, hc = i & 127;
        const float* gr = s_g + r * G4;
        float ig = sigf(gr[hc]);
        float fg = sigf(gr[HDIM + hc]);
        float gg = tanhf(gr[2 * HDIM + hc]);
        float og = sigf(gr[3 * HDIM + hc]);
        float c = fg * g_c[(row0 + r) * HDIM + hc] + ig * gg;
        float hn = og * tanhf(c);
        g_c[(row0 + r) * HDIM + hc] = c;
        g_hmid[(row0 + r) * HDIM + hc] = hn;
        s_h[r * HDIM + hc] = hn;
    }
    __syncthreads();
    if (tid < 32) {
        int r = tid >> 1, d = tid & 1;
        float a = b_hp[d];
        for (int k = 0; k < HDIM; k++) a += s_h[r * HDIM + k] * W_hp[k * 2 + d];
        s_rel[tid] = a;
        pred_out[row0 * 2 + tid] = a;
        g_pos[row0 * 2 + tid] = a + g_pos[row0 * 2 + tid];
    }
    __syncthreads();
    for (int i = tid; i < 16 * EDIM; i += 512) {
        int r = i >> 6, e = i & 63;
        g_decin[(row0 + r) * EDIM + e] =
            b_se[e] + s_rel[r * 2] * W_se[e] + s_rel[r * 2 + 1] * W_se[EDIM + e];
    }
}

// ---------------- per-j term: hterm[j] = h_new[j] @ W_p1[64:192] + cb ----------------
__global__ __launch_bounds__(512) void hterm_kernel(const float* __restrict__ W_p1) {
    __shared__ float s_h[16 * HDIM];
    int tid = threadIdx.x;
    int row0 = blockIdx.x * 16;
    for (int i = tid; i < 16 * HDIM; i += 512) s_h[i] = g_hmid[row0 * HDIM + i];
    __syncthreads();
    float acc[16];
    float cb = g_cb[tid];
#pragma unroll
    for (int r = 0; r < 16; r++) acc[r] = cb;
    for (int k = 0; k < HDIM; k++) {
        float w = W_p1[(EDIM + k) * P1D + tid];
#pragma unroll
        for (int r = 0; r < 16; r++) acc[r] += w * s_h[r * HDIM + k];
    }
#pragma unroll
    for (int r = 0; r < 16; r++) g_hterm[(row0 + r) * P1D + tid] = acc[r];
}

// ---------------- layer1: y = tf32(relu(hterm[j] + dx*M2[0] + dy*M2[1])); zero pool ----
__global__ __launch_bounds__(512) void layer1_kernel() {
    int s = blockIdx.x / NP, i = blockIdx.x % NP;
    int tid = threadIdx.x;
    __shared__ float sdx[NP], sdy[NP];
    if (tid < NP) {
        float xi = g_pos[(s * NP + i) * 2], yi = g_pos[(s * NP + i) * 2 + 1];
        sdx[tid] = g_pos[(s * NP + tid) * 2] - xi;
        sdy[tid] = g_pos[(s * NP + tid) * 2 + 1] - yi;
    }
    g_pool[(size_t)blockIdx.x * BNK + tid] = 0.f;
    g_pool[(size_t)blockIdx.x * BNK + P1D + tid] = 0.f;
    float m0 = g_M2[tid], m1 = g_M2[P1D + tid];
    __syncthreads();
    uint32_t* yout = (uint32_t*)(g_y + (size_t)blockIdx.x * NP * P1D);
#pragma unroll
    for (int j = 0; j < NP; j++) {
        float v = g_hterm[(s * NP + j) * P1D + tid] + sdx[j] * m0 + sdy[j] * m1;
        yout[j * P1D + tid] = f2tf32(fmaxf(v, 0.f));
    }
}

// ---------------- dominant GEMM: mma.sync tf32, cp.async double-buffered ----------------
// CTA tile M=128 x N=128, K=512 in 16 chunks of 32. 8 warps, warp tile 64x32.
#define GP_KC 32
#define APAD 36
#define ABUF (128 * APAD)   // floats per matrix per stage
#define DPAD 132
#define NCH (P1D / GP_KC)   // 16

__global__ __launch_bounds__(256) void gemm_pool_mma(const float* __restrict__ bp2) {
    extern __shared__ char smraw[];
    float* smem = (float*)smraw;
    float* Dsm = smem;                        // overlay for epilogue
    const int tid = threadIdx.x;
    const int wid = tid >> 5, lane = tid & 31;
    const int gid = lane >> 2, tig = lane & 3;
    const int wm = (wid & 1) * 64, wn = (wid >> 1) * 32;
    const int n0 = blockIdx.x * 128, R0 = blockIdx.y * 128;
    const float* Ag = g_y + (size_t)R0 * P1D;
    const float* Bg = g_Wp2t + (size_t)n0 * P1D;
    const uint32_t sb = smem_u32(smem);
    const int lrow = tid >> 3, lseg = (tid & 7) * 4;

    float acc[4][4][4] = {};

    // prologue: stage chunk 0 into buffer 0
#pragma unroll
    for (int p = 0; p < 4; p++) {
        int row = lrow + p * 32;
        uint32_t off = (uint32_t)(row * APAD + lseg) * 4;
        cp_async16(sb + off, Ag + (size_t)row * P1D + lseg);
        cp_async16(sb + ABUF * 4 + off, Bg + (size_t)row * P1D + lseg);
    }
    CP_COMMIT();

    for (int ch = 0; ch < NCH; ch++) {
        if (ch + 1 < NCH) {
            int kc = (ch + 1) * GP_KC;
            uint32_t bofs = ((ch + 1) & 1) * 2 * ABUF * 4;
#pragma unroll
            for (int p = 0; p < 4; p++) {
                int row = lrow + p * 32;
                uint32_t off = (uint32_t)(row * APAD + lseg) * 4;
                cp_async16(sb + bofs + off, Ag + (size_t)row * P1D + kc + lseg);
                cp_async16(sb + bofs + ABUF * 4 + off, Bg + (size_t)row * P1D + kc + lseg);
            }
            CP_COMMIT();
            CP_WAIT(1);
        } else {
            CP_WAIT(0);
        }
        __syncthreads();
        const uint32_t* Au = (const uint32_t*)(smem + (ch & 1) * 2 * ABUF);
        const uint32_t* Bu = Au + ABUF;
#pragma unroll
        for (int kk = 0; kk < GP_KC; kk += 8) {
            uint32_t af[4][4], bf[4][2];
#pragma unroll
            for (int mi = 0; mi < 4; mi++) {
                int r = wm + mi * 16 + gid;
                af[mi][0] = Au[r * APAD + kk + tig];
                af[mi][1] = Au[(r + 8) * APAD + kk + tig];
                af[mi][2] = Au[r * APAD + kk + tig + 4];
                af[mi][3] = Au[(r + 8) * APAD + kk + tig + 4];
            }
#pragma unroll
            for (int ni = 0; ni < 4; ni++) {
                int n = wn + ni * 8 + gid;
                bf[ni][0] = Bu[n * APAD + kk + tig];
                bf[ni][1] = Bu[n * APAD + kk + tig + 4];
            }
#pragma unroll
            for (int mi = 0; mi < 4; mi++)
#pragma unroll
                for (int ni = 0; ni < 4; ni++)
                    mma_tf32(acc[mi][ni], af[mi], bf[ni]);
        }
        __syncthreads();
    }

    // ---- epilogue: bias + relu into smem, per-ped max over 24 rows, atomicMax ----
#pragma unroll
    for (int mi = 0; mi < 4; mi++)
#pragma unroll
        for (int ni = 0; ni < 4; ni++) {
            int r = wm + mi * 16 + gid;
            int c = wn + ni * 8 + 2 * tig;
            float bv0 = bp2[n0 + c], bv1 = bp2[n0 + c + 1];
            Dsm[r * DPAD + c]           = fmaxf(acc[mi][ni][0] + bv0, 0.f);
            Dsm[r * DPAD + c + 1]       = fmaxf(acc[mi][ni][1] + bv1, 0.f);
            Dsm[(r + 8) * DPAD + c]     = fmaxf(acc[mi][ni][2] + bv0, 0.f);
            Dsm[(r + 8) * DPAD + c + 1] = fmaxf(acc[mi][ni][3] + bv1, 0.f);
        }
    __syncthreads();
    const int ped0 = R0 / NP;
    const int pedN = (R0 + 127) / NP - ped0 + 1;   // <= 6
    for (int it = tid; it < pedN * 128; it += 256) {
        int pl = it >> 7, c = it & 127;
        int gp = ped0 + pl;
        int rs = gp * NP - R0, re = rs + NP;
        if (rs < 0) rs = 0;
        if (re > 128) re = 128;
        float v = 0.f;
        for (int rr = rs; rr < re; rr++) v = fmaxf(v, Dsm[rr * DPAD + c]);
        atomicMax((int*)&g_pool[(size_t)gp * BNK + n0 + c], __float_as_int(v));
    }
}

// ---------------- mlp1 via mma.sync tf32: g_dh = relu([hmid|pool] @ W_m1 + b_m1) --------
// CTA tile M=64 x N=128, 8 warps of 32x32. K=1152 in 36 chunks of 32.
__global__ __launch_bounds__(256) void mlp1_mma(const float* __restrict__ bm1) {
    __shared__ float As[64 * APAD];
    __shared__ float Bs[128 * APAD];
    const uint32_t* Au = (const uint32_t*)As;
    const uint32_t* Bu = (const uint32_t*)Bs;
    const int tid = threadIdx.x;
    const int wid = tid >> 5, lane = tid & 31;
    const int gid = lane >> 2, tig = lane & 3;
    const int wm = (wid & 1) * 32, wn = (wid >> 1) * 32;
    const int n0 = blockIdx.x * 128, m0 = blockIdx.y * 64;
    const float* Bg = g_Wm1t + (size_t)n0 * KTOT;
    const uint32_t sbB = smem_u32(Bs);
    const int lrow = tid >> 3, lseg = (tid & 7) * 4;

    float acc[2][4][4] = {};

    for (int kc = 0; kc < KTOT; kc += GP_KC) {
        // B: cp.async (already tf32)
#pragma unroll
        for (int p = 0; p < 4; p++) {
            int row = lrow + p * 32;
            cp_async16(sbB + (uint32_t)(row * APAD + lseg) * 4,
                       Bg + (size_t)row * KTOT + kc + lseg);
        }
        CP_COMMIT();
        // A: load fp32, round to tf32, store (2 rows' worth per thread)
#pragma unroll
        for (int p = 0; p < 2; p++) {
            int row = lrow + p * 32;
            if (row < 64) {
                int k = kc + lseg;
                float4 v;
                if (k < HDIM) v = *(const float4*)(g_hmid + (size_t)(m0 + row) * HDIM + k);
                else v = *(const float4*)(g_pool + (size_t)(m0 + row) * BNK + (k - HDIM));
                uint32_t* da = (uint32_t*)(As + row * APAD + lseg);
                da[0] = f2tf32(v.x); da[1] = f2tf32(v.y);
                da[2] = f2tf32(v.z); da[3] = f2tf32(v.w);
            }
        }
        CP_WAIT(0);
        __syncthreads();
#pragma unroll
        for (int kk = 0; kk < GP_KC; kk += 8) {
            uint32_t af[2][4], bf[4][2];
#pragma unroll
            for (int mi = 0; mi < 2; mi++) {
                int r = wm + mi * 16 + gid;
                af[mi][0] = Au[r * APAD + kk + tig];
                af[mi][1] = Au[(r + 8) * APAD + kk + tig];
                af[mi][2] = Au[r * APAD + kk + tig + 4];
                af[mi][3] = Au[(r + 8) * APAD + kk + tig + 4];
            }
#pragma unroll
            for (int ni = 0; ni < 4; ni++) {
                int n = wn + ni * 8 + gid;
                bf[ni][0] = Bu[n * APAD + kk + tig];
                bf[ni][1] = Bu[n * APAD + kk + tig + 4];
            }
#pragma unroll
            for (int mi = 0; mi < 2; mi++)
#pragma unroll
                for (int ni = 0; ni < 4; ni++)
                    mma_tf32(acc[mi][ni], af[mi], bf[ni]);
        }
        __syncthreads();
    }
#pragma unroll
    for (int mi = 0; mi < 2; mi++)
#pragma unroll
        for (int ni = 0; ni < 4; ni++) {
            int r = m0 + wm + mi * 16 + gid;
            int c = n0 + wn + ni * 8 + 2 * tig;
            float bv0 = bm1[c], bv1 = bm1[c + 1];
            g_dh[(size_t)r * MLPD + c]           = fmaxf(acc[mi][ni][0] + bv0, 0.f);
            g_dh[(size_t)r * MLPD + c + 1]       = fmaxf(acc[mi][ni][1] + bv1, 0.f);
            g_dh[(size_t)(r + 8) * MLPD + c]     = fmaxf(acc[mi][ni][2] + bv0, 0.f);
            g_dh[(size_t)(r + 8) * MLPD + c + 1] = fmaxf(acc[mi][ni][3] + bv1, 0.f);
        }
}

// ---------------- decoder MLP layer 2: h = relu(dh @ W_m2 + b_m2) ----------------
__global__ __launch_bounds__(256) void mlp2_kernel(const float* __restrict__ Wm2,
                                                   const float* __restrict__ bm2) {
    const int m0 = blockIdx.x * 32;
    const int tid = threadIdx.x, tx = tid & 15, ty = tid >> 4;
    __shared__ float As[32][KC + 1];
    __shared__ float Bs[KC][128];
    float acc[2][8];
#pragma unroll
    for (int mm = 0; mm < 2; mm++)
#pragma unroll
        for (int nn = 0; nn < 8; nn++) acc[mm][nn] = 0.f;

    for (int kc = 0; kc < MLPD; kc += KC) {
#pragma unroll
        for (int p = 0; p < 2; p++) {
            int idx = tid + p * 256;
            int m = idx >> 4, kk = idx & 15;
            As[m][kk] = g_dh[(size_t)(m0 + m) * MLPD + kc + kk];
        }
#pragma unroll
        for (int p = 0; p < 8; p++) {
            int idx = tid + p * 256;
            int kk = idx >> 7, nn = idx & 127;
            Bs[kk][nn] = Wm2[(size_t)(kc + kk) * HDIM + nn];
        }
        __syncthreads();
#pragma unroll
        for (int kk = 0; kk < KC; kk++) {
            float a[2];
            a[0] = As[ty * 2][kk];
            a[1] = As[ty * 2 + 1][kk];
            float4 b0 = *(const float4*)&Bs[kk][tx * 8];
            float4 b1 = *(const float4*)&Bs[kk][tx * 8 + 4];
#pragma unroll
            for (int mm = 0; mm < 2; mm++) {
                acc[mm][0] += a[mm] * b0.x; acc[mm][1] += a[mm] * b0.y;
                acc[mm][2] += a[mm] * b0.z; acc[mm][3] += a[mm] * b0.w;
                acc[mm][4] += a[mm] * b1.x; acc[mm][5] += a[mm] * b1.y;
                acc[mm][6] += a[mm] * b1.z; acc[mm][7] += a[mm] * b1.w;
            }
        }
        __syncthreads();
    }
#pragma unroll
    for (int mm = 0; mm < 2; mm++)
#pragma unroll
        for (int nn = 0; nn < 8; nn++) {
            int n = tx * 8 + nn;
            g_h[(size_t)(m0 + ty * 2 + mm) * HDIM + n] = fmaxf(acc[mm][nn] + bm2[n], 0.f);
        }
}

__global__ void copy_h_kernel(float* __restrict__ out) {
    int i = blockIdx.x * blockDim.x + threadIdx.x;
    if (i < BATCH * HDIM) out[i] = g_h[i];
}

// ---------------- launch ----------------
#define SMEM_GP (4 * ABUF * 4 > 128 * DPAD * 4 ? 4 * ABUF * 4 : 128 * DPAD * 4)

extern "C" void kernel_launch(void* const* d_in, const int* in_sizes, int n_in,
                              void* d_out, int out_size) {
    const float* last_pos     = (const float*)d_in[0];
    const float* last_pos_rel = (const float*)d_in[1];
    const float* h0   = (const float*)d_in[2];
    const float* c0   = (const float*)d_in[3];
    /* d_in[4] = seq_start_end (uniform scenes; unused) */
    const float* W_se = (const float*)d_in[5];
    const float* b_se = (const float*)d_in[6];
    const float* W_ih = (const float*)d_in[7];
    const float* b_ih = (const float*)d_in[8];
    const float* W_hh = (const float*)d_in[9];
    const float* b_hh = (const float*)d_in[10];
    const float* W_hp = (const float*)d_in[11];
    const float* b_hp = (const float*)d_in[12];
    const float* W_pse = (const float*)d_in[13];
    const float* b_pse = (const float*)d_in[14];
    const float* W_p1 = (const float*)d_in[15];
    const float* b_p1 = (const float*)d_in[16];
    const float* W_p2 = (const float*)d_in[17];
    const float* b_p2 = (const float*)d_in[18];
    const float* W_m1 = (const float*)d_in[19];
    const float* b_m1 = (const float*)d_in[20];
    const float* W_m2 = (const float*)d_in[21];
    const float* b_m2 = (const float*)d_in[22];
    float* out = (float*)d_out;

    cudaFuncSetAttribute(gemm_pool_mma, cudaFuncAttributeMaxDynamicSharedMemorySize, SMEM_GP);

    setup_kernel<<<96, 256>>>(last_pos, last_pos_rel, h0, c0, W_se, b_se, W_pse, b_pse,
                              W_p1, b_p1, W_p2, W_m1);
    for (int t = 0; t < TSTEPS; t++) {
        lstm_kernel<<<BATCH / 16, 512>>>(W_ih, b_ih, W_hh, b_hh, W_hp, b_hp, W_se, b_se,
                                         out + (size_t)t * BATCH * 2);
        hterm_kernel<<<BATCH / 16, 512>>>(W_p1);
        layer1_kernel<<<BATCH, 512>>>();
        gemm_pool_mma<<<dim3(BNK / 128, (BATCH * NP) / 128), 256, SMEM_GP>>>(b_p2);
        mlp1_mma<<<dim3(BNK / 128, BATCH / 64), 256>>>(b_m1);
        mlp2_kernel<<<24, 256>>>(W_m2, b_m2);
    }
    copy_h_kernel<<<(BATCH * HDIM + 255) / 256, 256>>>(out + TSTEPS * BATCH * 2);
}

// round 5
// speedup vs baseline: 3.2147x; 1.2776x over previous
#include <cuda_runtime.h>
#include <cuda_fp16.h>
#include <math.h>
#include <stdint.h>

#define BATCH 768
#define NS 32
#define NP 24
#define EDIM 64
#define HDIM 128
#define G4 512      // 4*HDIM
#define P1D 512     // pool hidden
#define BNK 1024
#define MLPD 1024
#define KTOT (HDIM + BNK)   // 1152
#define TSTEPS 12
#define KC 16

// ---------------- scratch (static device memory; no allocations) ----------------
__device__ float g_pos[BATCH * 2];
__device__ float g_decin[BATCH * EDIM];
__device__ float g_h[BATCH * HDIM];
__device__ float g_c[BATCH * HDIM];
__device__ float g_hmid[BATCH * HDIM];
__device__ float g_hterm[BATCH * P1D];
__device__ __half g_y[(size_t)BATCH * NP * P1D];   // fp16
__device__ float g_pool[(size_t)BATCH * BNK];
__device__ float g_dh[(size_t)BATCH * MLPD];
__device__ float g_M2[2 * P1D];
__device__ float g_cb[P1D];
__device__ __half g_Wp2t[(size_t)BNK * P1D];       // W_p2^T fp16
__device__ __half g_Wm1t[(size_t)MLPD * KTOT];     // W_m1^T fp16

__device__ __forceinline__ float sigf(float x) { return 1.f / (1.f + expf(-x)); }

// warp-level fp16 HMMA (generic PTX, sm_80+): m16n8k16, fp32 accum
__device__ __forceinline__ void mma_f16(float* d, const uint32_t* a, const uint32_t* b) {
    asm volatile(
        "mma.sync.aligned.m16n8k16.row.col.f32.f16.f16.f32 "
        "{%0,%1,%2,%3}, {%4,%5,%6,%7}, {%8,%9}, {%0,%1,%2,%3};"
        : "+f"(d[0]), "+f"(d[1]), "+f"(d[2]), "+f"(d[3])
        : "r"(a[0]), "r"(a[1]), "r"(a[2]), "r"(a[3]), "r"(b[0]), "r"(b[1]));
}

__device__ __forceinline__ uint32_t smem_u32(const void* p) {
    uint32_t a;
    asm("{ .reg .u64 t; cvta.to.shared.u64 t, %1; cvt.u32.u64 %0, t; }" : "=r"(a) : "l"(p));
    return a;
}
__device__ __forceinline__ void cp_async16(uint32_t saddr, const void* g) {
    asm volatile("cp.async.cg.shared.global [%0], [%1], 16;" :: "r"(saddr), "l"(g));
}
#define CP_COMMIT() asm volatile("cp.async.commit_group;" ::: "memory")
#define CP_WAIT(n)  asm volatile("cp.async.wait_group %0;" :: "n"(n) : "memory")

// ---------------- setup ----------------
__global__ void setup_kernel(const float* __restrict__ last_pos,
                             const float* __restrict__ last_pos_rel,
                             const float* __restrict__ h0, const float* __restrict__ c0,
                             const float* __restrict__ W_se, const float* __restrict__ b_se,
                             const float* __restrict__ W_pse, const float* __restrict__ b_pse,
                             const float* __restrict__ W_p1, const float* __restrict__ b_p1,
                             const float* __restrict__ W_p2, const float* __restrict__ W_m1) {
    int tid = blockIdx.x * blockDim.x + threadIdx.x;
    int nt = gridDim.x * blockDim.x;
    for (int i = tid; i < BATCH * 2; i += nt) g_pos[i] = last_pos[i];
    for (int i = tid; i < BATCH * HDIM; i += nt) { g_h[i] = h0[i]; g_c[i] = c0[i]; }
    for (int i = tid; i < BATCH * EDIM; i += nt) {
        int b = i >> 6, e = i & 63;
        g_decin[i] = b_se[e] + last_pos_rel[b * 2] * W_se[e] + last_pos_rel[b * 2 + 1] * W_se[EDIM + e];
    }
    for (int i = tid; i < 2 * P1D; i += nt) {
        int d = i >> 9, t = i & 511;
        float a = 0.f;
        for (int e = 0; e < EDIM; e++) a += W_pse[d * EDIM + e] * W_p1[e * P1D + t];
        g_M2[i] = a;
    }
    for (int i = tid; i < P1D; i += nt) {
        float a = b_p1[i];
        for (int e = 0; e < EDIM; e++) a += b_pse[e] * W_p1[e * P1D + i];
        g_cb[i] = a;
    }
    for (int i = tid; i < BNK * P1D; i += nt) {
        int n = i / P1D, k = i % P1D;
        g_Wp2t[i] = __float2half_rn(W_p2[(size_t)k * BNK + n]);
    }
    for (int i = tid; i < MLPD * KTOT; i += nt) {
        int n = i / KTOT, k = i % KTOT;
        g_Wm1t[i] = __float2half_rn(W_m1[(size_t)k * MLPD + n]);
    }
}

// ---------------- fused LSTM step + hidden2pos + pos update + next dec_in ----------------
__global__ __launch_bounds__(512) void lstm_kernel(
    const float* __restrict__ W_ih, const float* __restrict__ b_ih,
    const float* __restrict__ W_hh, const float* __restrict__ b_hh,
    const float* __restrict__ W_hp, const float* __restrict__ b_hp,
    const float* __restrict__ W_se, const float* __restrict__ b_se,
    float* __restrict__ pred_out) {
    __shared__ float s_x[16 * EDIM];
    __shared__ float s_h[16 * HDIM];
    __shared__ float s_g[16 * G4];
    __shared__ float s_rel[32];
    int tid = threadIdx.x;
    int row0 = blockIdx.x * 16;
    for (int i = tid; i < 16 * EDIM; i += 512) s_x[i] = g_decin[row0 * EDIM + i];
    for (int i = tid; i < 16 * HDIM; i += 512) s_h[i] = g_h[row0 * HDIM + i];
    __syncthreads();
    {
        float acc[16];
        float bb = b_ih[tid] + b_hh[tid];
#pragma unroll
        for (int r = 0; r < 16; r++) acc[r] = bb;
        for (int k = 0; k < EDIM; k++) {
            float w = W_ih[k * G4 + tid];
#pragma unroll
            for (int r = 0; r < 16; r++) acc[r] += w * s_x[r * EDIM + k];
        }
        for (int k = 0; k < HDIM; k++) {
            float w = W_hh[k * G4 + tid];
#pragma unroll
            for (int r = 0; r < 16; r++) acc[r] += w * s_h[r * HDIM + k];
        }
#pragma unroll
        for (int r = 0; r < 16; r++) s_g[r * G4 + tid] = acc[r];
    }
    __syncthreads();
    for (int i = tid; i < 16 * HDIM; i += 512) {
        int r = i >> 7, hc = i & 127;
        const float* gr = s_g + r * G4;
        float ig = sigf(gr[hc]);
        float fg = sigf(gr[HDIM + hc]);
        float gg = tanhf(gr[2 * HDIM + hc]);
        float og = sigf(gr[3 * HDIM + hc]);
        float c = fg * g_c[(row0 + r) * HDIM + hc] + ig * gg;
        float hn = og * tanhf(c);
        g_c[(row0 + r) * HDIM + hc] = c;
        g_hmid[(row0 + r) * HDIM + hc] = hn;
        s_h[r * HDIM + hc] = hn;
    }
    __syncthreads();
    if (tid < 32) {
        int r = tid >> 1, d = tid & 1;
        float a = b_hp[d];
        for (int k = 0; k < HDIM; k++) a += s_h[r * HDIM + k] * W_hp[k * 2 + d];
        s_rel[tid] = a;
        pred_out[row0 * 2 + tid] = a;
        g_pos[row0 * 2 + tid] = a + g_pos[row0 * 2 + tid];
    }
    __syncthreads();
    for (int i = tid; i < 16 * EDIM; i += 512) {
        int r = i >> 6, e = i & 63;
        g_decin[(row0 + r) * EDIM + e] =
            b_se[e] + s_rel[r * 2] * W_se[e] + s_rel[r * 2 + 1] * W_se[EDIM + e];
    }
}

// ---------------- per-j term: hterm[j] = h_new[j] @ W_p1[64:192] + cb ----------------
__global__ __launch_bounds__(512) void hterm_kernel(const float* __restrict__ W_p1) {
    __shared__ float s_h[16 * HDIM];
    int tid = threadIdx.x;
    int row0 = blockIdx.x * 16;
    for (int i = tid; i < 16 * HDIM; i += 512) s_h[i] = g_hmid[row0 * HDIM + i];
    __syncthreads();
    float acc[16];
    float cb = g_cb[tid];
#pragma unroll
    for (int r = 0; r < 16; r++) acc[r] = cb;
    for (int k = 0; k < HDIM; k++) {
        float w = W_p1[(EDIM + k) * P1D + tid];
#pragma unroll
        for (int r = 0; r < 16; r++) acc[r] += w * s_h[r * HDIM + k];
    }
#pragma unroll
    for (int r = 0; r < 16; r++) g_hterm[(row0 + r) * P1D + tid] = acc[r];
}

// ---------------- layer1: y = fp16(relu(hterm[j] + dx*M2[0] + dy*M2[1])); zero pool ----
__global__ __launch_bounds__(512) void layer1_kernel() {
    int s = blockIdx.x / NP, i = blockIdx.x % NP;
    int tid = threadIdx.x;
    __shared__ float sdx[NP], sdy[NP];
    if (tid < NP) {
        float xi = g_pos[(s * NP + i) * 2], yi = g_pos[(s * NP + i) * 2 + 1];
        sdx[tid] = g_pos[(s * NP + tid) * 2] - xi;
        sdy[tid] = g_pos[(s * NP + tid) * 2 + 1] - yi;
    }
    g_pool[(size_t)blockIdx.x * BNK + tid] = 0.f;
    g_pool[(size_t)blockIdx.x * BNK + P1D + tid] = 0.f;
    float m0 = g_M2[tid], m1 = g_M2[P1D + tid];
    __syncthreads();
    __half* yout = g_y + (size_t)blockIdx.x * NP * P1D;
#pragma unroll
    for (int j = 0; j < NP; j++) {
        float v = g_hterm[(s * NP + j) * P1D + tid] + sdx[j] * m0 + sdy[j] * m1;
        yout[j * P1D + tid] = __float2half_rn(fmaxf(v, 0.f));
    }
}

// ---------------- dominant GEMM: mma.sync fp16, cp.async double-buffered ----------------
// CTA tile M=128 x N=128, K=512 in 8 chunks of 64. 8 warps, warp tile 64x32.
#define GP_KC 64          // halves per chunk
#define KP 72             // smem stride in halves (word-stride 36 == 4 mod 32)
#define STAGEB 36864      // bytes per stage (A 18432 + B 18432)
#define MATB 18432
#define DPAD 132
#define NCH (P1D / GP_KC) // 8

__global__ __launch_bounds__(256) void gemm_pool_mma(const float* __restrict__ bp2) {
    extern __shared__ char smraw[];
    float* Dsm = (float*)smraw;               // overlay for epilogue
    const int tid = threadIdx.x;
    const int wid = tid >> 5, lane = tid & 31;
    const int gid = lane >> 2, tig = lane & 3;
    const int wm = (wid & 1) * 64, wn = (wid >> 1) * 32;
    const int n0 = blockIdx.x * 128, R0 = blockIdx.y * 128;
    const __half* Ag = g_y + (size_t)R0 * P1D;
    const __half* Bg = g_Wp2t + (size_t)n0 * P1D;
    const uint32_t sb = smem_u32(smraw);
    const int lrow = tid >> 3;                // 0..31
    const int lcol = (tid & 7) * 8;           // halves

    float acc[4][4][4] = {};

    // prologue: stage chunk 0 into buffer 0
#pragma unroll
    for (int p = 0; p < 4; p++) {
        int row = lrow + p * 32;
        uint32_t off = (uint32_t)(row * KP + lcol) * 2;
        cp_async16(sb + off, Ag + (size_t)row * P1D + lcol);
        cp_async16(sb + MATB + off, Bg + (size_t)row * P1D + lcol);
    }
    CP_COMMIT();

    for (int ch = 0; ch < NCH; ch++) {
        if (ch + 1 < NCH) {
            int kc = (ch + 1) * GP_KC;
            uint32_t bofs = ((ch + 1) & 1) * STAGEB;
#pragma unroll
            for (int p = 0; p < 4; p++) {
                int row = lrow + p * 32;
                uint32_t off = (uint32_t)(row * KP + lcol) * 2;
                cp_async16(sb + bofs + off, Ag + (size_t)row * P1D + kc + lcol);
                cp_async16(sb + bofs + MATB + off, Bg + (size_t)row * P1D + kc + lcol);
            }
            CP_COMMIT();
            CP_WAIT(1);
        } else {
            CP_WAIT(0);
        }
        __syncthreads();
        const uint32_t* Au = (const uint32_t*)(smraw + (ch & 1) * STAGEB);
        const uint32_t* Bu = (const uint32_t*)(smraw + (ch & 1) * STAGEB + MATB);
#pragma unroll
        for (int kk = 0; kk < GP_KC; kk += 16) {
            const int kw = kk >> 1;
            uint32_t af[4][4], bf[4][2];
#pragma unroll
            for (int mi = 0; mi < 4; mi++) {
                int r = wm + mi * 16 + gid;
                af[mi][0] = Au[r * 36 + kw + tig];
                af[mi][1] = Au[(r + 8) * 36 + kw + tig];
                af[mi][2] = Au[r * 36 + kw + tig + 4];
                af[mi][3] = Au[(r + 8) * 36 + kw + tig + 4];
            }
#pragma unroll
            for (int ni = 0; ni < 4; ni++) {
                int n = wn + ni * 8 + gid;
                bf[ni][0] = Bu[n * 36 + kw + tig];
                bf[ni][1] = Bu[n * 36 + kw + tig + 4];
            }
#pragma unroll
            for (int mi = 0; mi < 4; mi++)
#pragma unroll
                for (int ni = 0; ni < 4; ni++)
                    mma_f16(acc[mi][ni], af[mi], bf[ni]);
        }
        __syncthreads();
    }

    // ---- epilogue: bias + relu into smem, per-ped max over 24 rows, atomicMax ----
#pragma unroll
    for (int mi = 0; mi < 4; mi++)
#pragma unroll
        for (int ni = 0; ni < 4; ni++) {
            int r = wm + mi * 16 + gid;
            int c = wn + ni * 8 + 2 * tig;
            float bv0 = bp2[n0 + c], bv1 = bp2[n0 + c + 1];
            Dsm[r * DPAD + c]           = fmaxf(acc[mi][ni][0] + bv0, 0.f);
            Dsm[r * DPAD + c + 1]       = fmaxf(acc[mi][ni][1] + bv1, 0.f);
            Dsm[(r + 8) * DPAD + c]     = fmaxf(acc[mi][ni][2] + bv0, 0.f);
            Dsm[(r + 8) * DPAD + c + 1] = fmaxf(acc[mi][ni][3] + bv1, 0.f);
        }
    __syncthreads();
    const int ped0 = R0 / NP;
    const int pedN = (R0 + 127) / NP - ped0 + 1;   // <= 6
    for (int it = tid; it < pedN * 128; it += 256) {
        int pl = it >> 7, c = it & 127;
        int gp = ped0 + pl;
        int rs = gp * NP - R0, re = rs + NP;
        if (rs < 0) rs = 0;
        if (re > 128) re = 128;
        float v = 0.f;
        for (int rr = rs; rr < re; rr++) v = fmaxf(v, Dsm[rr * DPAD + c]);
        atomicMax((int*)&g_pool[(size_t)gp * BNK + n0 + c], __float_as_int(v));
    }
}

// ---------------- mlp1 via mma.sync fp16: g_dh = relu([hmid|pool] @ W_m1 + b_m1) --------
// CTA tile M=64 x N=128, 8 warps of 32x32. K=1152 in 18 chunks of 64.
__global__ __launch_bounds__(256) void mlp1_mma(const float* __restrict__ bm1) {
    __shared__ __half As[64 * KP];
    __shared__ __half Bs[128 * KP];
    const uint32_t* Au = (const uint32_t*)As;
    const uint32_t* Bu = (const uint32_t*)Bs;
    const int tid = threadIdx.x;
    const int wid = tid >> 5, lane = tid & 31;
    const int gid = lane >> 2, tig = lane & 3;
    const int wm = (wid & 1) * 32, wn = (wid >> 1) * 32;
    const int n0 = blockIdx.x * 128, m0 = blockIdx.y * 64;
    const __half* Bg = g_Wm1t + (size_t)n0 * KTOT;
    const uint32_t sbB = smem_u32(Bs);
    const int lrow = tid >> 3;
    const int lcol = (tid & 7) * 8;

    float acc[2][4][4] = {};

    for (int kc = 0; kc < KTOT; kc += GP_KC) {
        // B: cp.async (already fp16)
#pragma unroll
        for (int p = 0; p < 4; p++) {
            int row = lrow + p * 32;
            cp_async16(sbB + (uint32_t)(row * KP + lcol) * 2,
                       Bg + (size_t)row * KTOT + kc + lcol);
        }
        CP_COMMIT();
        // A: load fp32, convert to fp16 (8 values per thread per row-pass)
#pragma unroll
        for (int p = 0; p < 2; p++) {
            int row = lrow + p * 32;
            int k = kc + lcol;
            const float* src = (k < HDIM) ? (g_hmid + (size_t)(m0 + row) * HDIM + k)
                                          : (g_pool + (size_t)(m0 + row) * BNK + (k - HDIM));
            float4 v0 = ((const float4*)src)[0];
            float4 v1 = ((const float4*)src)[1];
            __half2* da = (__half2*)(As + row * KP + lcol);
            da[0] = __floats2half2_rn(v0.x, v0.y);
            da[1] = __floats2half2_rn(v0.z, v0.w);
            da[2] = __floats2half2_rn(v1.x, v1.y);
            da[3] = __floats2half2_rn(v1.z, v1.w);
        }
        CP_WAIT(0);
        __syncthreads();
#pragma unroll
        for (int kk = 0; kk < GP_KC; kk += 16) {
            const int kw = kk >> 1;
            uint32_t af[2][4], bf[4][2];
#pragma unroll
            for (int mi = 0; mi < 2; mi++) {
                int r = wm + mi * 16 + gid;
                af[mi][0] = Au[r * 36 + kw + tig];
                af[mi][1] = Au[(r + 8) * 36 + kw + tig];
                af[mi][2] = Au[r * 36 + kw + tig + 4];
                af[mi][3] = Au[(r + 8) * 36 + kw + tig + 4];
            }
#pragma unroll
            for (int ni = 0; ni < 4; ni++) {
                int n = wn + ni * 8 + gid;
                bf[ni][0] = Bu[n * 36 + kw + tig];
                bf[ni][1] = Bu[n * 36 + kw + tig + 4];
            }
#pragma unroll
            for (int mi = 0; mi < 2; mi++)
#pragma unroll
                for (int ni = 0; ni < 4; ni++)
                    mma_f16(acc[mi][ni], af[mi], bf[ni]);
        }
        __syncthreads();
    }
#pragma unroll
    for (int mi = 0; mi < 2; mi++)
#pragma unroll
        for (int ni = 0; ni < 4; ni++) {
            int r = m0 + wm + mi * 16 + gid;
            int c = n0 + wn + ni * 8 + 2 * tig;
            float bv0 = bm1[c], bv1 = bm1[c + 1];
            g_dh[(size_t)r * MLPD + c]           = fmaxf(acc[mi][ni][0] + bv0, 0.f);
            g_dh[(size_t)r * MLPD + c + 1]       = fmaxf(acc[mi][ni][1] + bv1, 0.f);
            g_dh[(size_t)(r + 8) * MLPD + c]     = fmaxf(acc[mi][ni][2] + bv0, 0.f);
            g_dh[(size_t)(r + 8) * MLPD + c + 1] = fmaxf(acc[mi][ni][3] + bv1, 0.f);
        }
}

// ---------------- decoder MLP layer 2: h = relu(dh @ W_m2 + b_m2) ----------------
__global__ __launch_bounds__(256) void mlp2_kernel(const float* __restrict__ Wm2,
                                                   const float* __restrict__ bm2) {
    const int m0 = blockIdx.x * 32;
    const int tid = threadIdx.x, tx = tid & 15, ty = tid >> 4;
    __shared__ float As[32][KC + 1];
    __shared__ float Bs[KC][128];
    float acc[2][8];
#pragma unroll
    for (int mm = 0; mm < 2; mm++)
#pragma unroll
        for (int nn = 0; nn < 8; nn++) acc[mm][nn] = 0.f;

    for (int kc = 0; kc < MLPD; kc += KC) {
#pragma unroll
        for (int p = 0; p < 2; p++) {
            int idx = tid + p * 256;
            int m = idx >> 4, kk = idx & 15;
            As[m][kk] = g_dh[(size_t)(m0 + m) * MLPD + kc + kk];
        }
#pragma unroll
        for (int p = 0; p < 8; p++) {
            int idx = tid + p * 256;
            int kk = idx >> 7, nn = idx & 127;
            Bs[kk][nn] = Wm2[(size_t)(kc + kk) * HDIM + nn];
        }
        __syncthreads();
#pragma unroll
        for (int kk = 0; kk < KC; kk++) {
            float a[2];
            a[0] = As[ty * 2][kk];
            a[1] = As[ty * 2 + 1][kk];
            float4 b0 = *(const float4*)&Bs[kk][tx * 8];
            float4 b1 = *(const float4*)&Bs[kk][tx * 8 + 4];
#pragma unroll
            for (int mm = 0; mm < 2; mm++) {
                acc[mm][0] += a[mm] * b0.x; acc[mm][1] += a[mm] * b0.y;
                acc[mm][2] += a[mm] * b0.z; acc[mm][3] += a[mm] * b0.w;
                acc[mm][4] += a[mm] * b1.x; acc[mm][5] += a[mm] * b1.y;
                acc[mm][6] += a[mm] * b1.z; acc[mm][7] += a[mm] * b1.w;
            }
        }
        __syncthreads();
    }
#pragma unroll
    for (int mm = 0; mm < 2; mm++)
#pragma unroll
        for (int nn = 0; nn < 8; nn++) {
            int n = tx * 8 + nn;
            g_h[(size_t)(m0 + ty * 2 + mm) * HDIM + n] = fmaxf(acc[mm][nn] + bm2[n], 0.f);
        }
}

__global__ void copy_h_kernel(float* __restrict__ out) {
    int i = blockIdx.x * blockDim.x + threadIdx.x;
    if (i < BATCH * HDIM) out[i] = g_h[i];
}

// ---------------- launch ----------------
#define SMEM_GP (2 * STAGEB > 128 * DPAD * 4 ? 2 * STAGEB : 128 * DPAD * 4)

extern "C" void kernel_launch(void* const* d_in, const int* in_sizes, int n_in,
                              void* d_out, int out_size) {
    const float* last_pos     = (const float*)d_in[0];
    const float* last_pos_rel = (const float*)d_in[1];
    const float* h0   = (const float*)d_in[2];
    const float* c0   = (const float*)d_in[3];
    /* d_in[4] = seq_start_end (uniform scenes; unused) */
    const float* W_se = (const float*)d_in[5];
    const float* b_se = (const float*)d_in[6];
    const float* W_ih = (const float*)d_in[7];
    const float* b_ih = (const float*)d_in[8];
    const float* W_hh = (const float*)d_in[9];
    const float* b_hh = (const float*)d_in[10];
    const float* W_hp = (const float*)d_in[11];
    const float* b_hp = (const float*)d_in[12];
    const float* W_pse = (const float*)d_in[13];
    const float* b_pse = (const float*)d_in[14];
    const float* W_p1 = (const float*)d_in[15];
    const float* b_p1 = (const float*)d_in[16];
    const float* W_p2 = (const float*)d_in[17];
    const float* b_p2 = (const float*)d_in[18];
    const float* W_m1 = (const float*)d_in[19];
    const float* b_m1 = (const float*)d_in[20];
    const float* W_m2 = (const float*)d_in[21];
    const float* b_m2 = (const float*)d_in[22];
    float* out = (float*)d_out;

    cudaFuncSetAttribute(gemm_pool_mma, cudaFuncAttributeMaxDynamicSharedMemorySize, SMEM_GP);

    setup_kernel<<<96, 256>>>(last_pos, last_pos_rel, h0, c0, W_se, b_se, W_pse, b_pse,
                              W_p1, b_p1, W_p2, W_m1);
    for (int t = 0; t < TSTEPS; t++) {
        lstm_kernel<<<BATCH / 16, 512>>>(W_ih, b_ih, W_hh, b_hh, W_hp, b_hp, W_se, b_se,
                                         out + (size_t)t * BATCH * 2);
        hterm_kernel<<<BATCH / 16, 512>>>(W_p1);
        layer1_kernel<<<BATCH, 512>>>();
        gemm_pool_mma<<<dim3(BNK / 128, (BATCH * NP) / 128), 256, SMEM_GP>>>(b_p2);
        mlp1_mma<<<dim3(BNK / 128, BATCH / 64), 256>>>(b_m1);
        mlp2_kernel<<<24, 256>>>(W_m2, b_m2);
    }
    copy_h_kernel<<<(BATCH * HDIM + 255) / 256, 256>>>(out + TSTEPS * BATCH * 2);
}